// round 8
// baseline (speedup 1.0000x reference)
#include <cuda_runtime.h>
#include <math.h>

#define C_DIM 128
#define S_DIM 4096
#define HW 176          // 16 * 11
#define HW4 44          // HW / 4
#define B_SEG 32
#define O_DIM 256
#define OBLK 32         // o per block
#define PART_LEN 44     // 4 rows * 11
#define GEM_EPS 1e-6f
#define NEG_INF -3.402823466e38f

// scratch
__device__ float g_pooled[B_SEG * C_DIM * HW];   // [b][c][hw]
__device__ float g_Wt[C_DIM * O_DIM];            // [c][o]  (transposed W)

__device__ __forceinline__ float4 max4(float4 a, float4 b) {
    float4 r;
    r.x = fmaxf(a.x, b.x); r.y = fmaxf(a.y, b.y);
    r.z = fmaxf(a.z, b.z); r.w = fmaxf(a.w, b.w);
    return r;
}

__device__ __forceinline__ unsigned long long pack2(float v) {
    unsigned long long r;
    asm("mov.b64 %0, {%1, %1};" : "=l"(r) : "f"(v));
    return r;
}
__device__ __forceinline__ void unpack2(unsigned long long v, float& lo, float& hi) {
    asm("mov.b64 {%0, %1}, %2;" : "=f"(lo), "=f"(hi) : "l"(v));
}
__device__ __forceinline__ void ffma2(unsigned long long& d,
                                      unsigned long long a, unsigned long long b) {
    asm("fma.rn.f32x2 %0, %1, %2, %0;" : "+l"(d) : "l"(a), "l"(b));
}

// GeM power: v^pe. Fast path for pe == 6.5: (v^3)^2 * sqrt(v).
__device__ __forceinline__ float gem_pow(float x, float pe, bool fast65) {
    float v = fmaxf(x, GEM_EPS);
    if (fast65) {
        float v3 = v * v * v;
        return v3 * v3 * sqrtf(v);
    }
    return exp2f(pe * __log2f(v));
}

// ---------------------------------------------------------------------------
// Kernel 0: transpose W[o][c] -> g_Wt[c][o]. 128 blocks x 256 threads.
// ---------------------------------------------------------------------------
__global__ void wt_kernel(const float* __restrict__ Wmat)
{
    int cc = blockIdx.x;
    int o  = threadIdx.x;
    g_Wt[cc * O_DIM + o] = Wmat[o * C_DIM + cc];
}

// ---------------------------------------------------------------------------
// Kernel 1: ragged segment max, float4 streaming, evict-first, MLP=8.
// One block per (b, c); 352 threads = 8 s-groups x 44 f4-columns.
// At the ~6.3 TB/s LTS cap — leave alone.
// ---------------------------------------------------------------------------
__global__ void __launch_bounds__(352) seg_max_kernel(
    const float* __restrict__ x, const int* __restrict__ seqL)
{
    int blk = blockIdx.x;
    int b = blk & (B_SEG - 1);
    int c = blk >> 5;

    __shared__ int sh[2];
    __shared__ float4 sm[8 * HW4];

    if (threadIdx.x == 0) {
        int s0 = 0;
        #pragma unroll
        for (int i = 0; i < B_SEG; i++) s0 += (i < b) ? seqL[i] : 0;
        sh[0] = s0;
        sh[1] = seqL[b];
    }
    __syncthreads();

    int tid = threadIdx.x;
    int sg  = tid / HW4;   // 0..7
    int col = tid % HW4;   // 0..43

    int s0  = sh[0];
    int len = sh[1];

    const float4* bp = reinterpret_cast<const float4*>(x)
                     + (size_t)c * (S_DIM * HW4) + (size_t)s0 * HW4 + col;

    float4 m = make_float4(NEG_INF, NEG_INF, NEG_INF, NEG_INF);
    int s = sg;
    for (; s + 56 < len; s += 64) {
        float4 a0 = __ldcs(&bp[(size_t)(s +  0) * HW4]);
        float4 a1 = __ldcs(&bp[(size_t)(s +  8) * HW4]);
        float4 a2 = __ldcs(&bp[(size_t)(s + 16) * HW4]);
        float4 a3 = __ldcs(&bp[(size_t)(s + 24) * HW4]);
        float4 a4 = __ldcs(&bp[(size_t)(s + 32) * HW4]);
        float4 a5 = __ldcs(&bp[(size_t)(s + 40) * HW4]);
        float4 a6 = __ldcs(&bp[(size_t)(s + 48) * HW4]);
        float4 a7 = __ldcs(&bp[(size_t)(s + 56) * HW4]);
        m = max4(m, max4(max4(max4(a0, a1), max4(a2, a3)),
                         max4(max4(a4, a5), max4(a6, a7))));
    }
    for (; s < len; s += 8) {
        m = max4(m, __ldcs(&bp[(size_t)s * HW4]));
    }

    sm[sg * HW4 + col] = m;
    __syncthreads();

    if (tid < HW4) {
        float4 r = sm[tid];
        #pragma unroll
        for (int g = 1; g < 8; g++) r = max4(r, sm[g * HW4 + tid]);
        reinterpret_cast<float4*>(g_pooled)[(size_t)(b * C_DIM + c) * HW4 + tid] = r;
    }
}

// ---------------------------------------------------------------------------
// Kernel 2: fused 1x1 conv (FFMA2) + GeM — NO shared memory in main loop.
// Grid (8 o-blocks of 32, 32 b) = 256 blocks, 192 threads =
// 4 o-subtiles x 48 (44 active hw-quads). Per cc per thread:
//   1 LDG.128 pooled quad (coalesced) + 2 uniform LDG.128 of g_Wt (broadcast,
//   1 wavefront each, L1-hit) + 4 splat movs + 16 FFMA2 = 32 MACs.
// ---------------------------------------------------------------------------
__global__ void __launch_bounds__(192) conv_gem_kernel(
    const float* __restrict__ p, float* __restrict__ out)
{
    __shared__ float ypow[OBLK * HW];   // [o_local][hw], 22 KB
    __shared__ float pp[4];

    int b   = blockIdx.y;
    int tid = threadIdx.x;
    int sub = tid / 48;          // o-subtile 0..3
    int t   = tid % 48;          // hw-quad index, active < 44
    int o0  = blockIdx.x * OBLK + sub * 8;

    if (tid < 4) pp[tid] = p[tid];
    __syncthreads();

    if (t < HW4) {
        unsigned long long acc[16];   // [hw_in_quad/... 4 hw][4 o-pairs]
        #pragma unroll
        for (int k = 0; k < 16; k++) acc[k] = 0ULL;

        const float4* pb = reinterpret_cast<const float4*>(
            g_pooled + (size_t)b * C_DIM * HW) + t;
        const float* wt = g_Wt + o0;

        #pragma unroll 4
        for (int cc = 0; cc < C_DIM; cc++) {
            float4 pv = __ldg(&pb[(size_t)cc * HW4]);
            ulonglong2 w01 = __ldg(reinterpret_cast<const ulonglong2*>(
                wt + (size_t)cc * O_DIM));
            ulonglong2 w23 = __ldg(reinterpret_cast<const ulonglong2*>(
                wt + (size_t)cc * O_DIM + 4));

            unsigned long long px = pack2(pv.x);
            unsigned long long py = pack2(pv.y);
            unsigned long long pz = pack2(pv.z);
            unsigned long long pw = pack2(pv.w);

            ffma2(acc[ 0], px, w01.x); ffma2(acc[ 1], px, w01.y);
            ffma2(acc[ 2], px, w23.x); ffma2(acc[ 3], px, w23.y);
            ffma2(acc[ 4], py, w01.x); ffma2(acc[ 5], py, w01.y);
            ffma2(acc[ 6], py, w23.x); ffma2(acc[ 7], py, w23.y);
            ffma2(acc[ 8], pz, w01.x); ffma2(acc[ 9], pz, w01.y);
            ffma2(acc[10], pz, w23.x); ffma2(acc[11], pz, w23.y);
            ffma2(acc[12], pw, w01.x); ffma2(acc[13], pw, w01.y);
            ffma2(acc[14], pw, w23.x); ffma2(acc[15], pw, w23.y);
        }

        // GeM elementwise power. hw = 4t..4t+3, all in the same part
        // (44 = 4 * 11, quad never straddles a 44 boundary).
        int hw0  = 4 * t;
        float pe = pp[t / 11];
        bool fast65 = (pe == 6.5f);
        int ob = sub * 8;   // o_local base
        #pragma unroll
        for (int h = 0; h < 4; h++) {
            #pragma unroll
            for (int q = 0; q < 4; q++) {
                float lo, hi;
                unpack2(acc[h * 4 + q], lo, hi);
                ypow[(ob + 2 * q + 0) * HW + hw0 + h] = gem_pow(lo, pe, fast65);
                ypow[(ob + 2 * q + 1) * HW + hw0 + h] = gem_pow(hi, pe, fast65);
            }
        }
    }
    __syncthreads();

    // 128 threads: one per (o_local, part)
    if (tid < OBLK * 4) {
        int ol   = tid >> 2;
        int part = tid & 3;
        const float* yp = ypow + ol * HW + part * PART_LEN;
        float sum = 0.0f;
        #pragma unroll
        for (int k = 0; k < PART_LEN; k++) sum += yp[k];
        float pe = pp[part];
        float mean = sum * (1.0f / (float)PART_LEN);
        float g = (mean > 0.0f) ? exp2f(__log2f(mean) / pe) : 0.0f;
        out[((size_t)b * O_DIM + blockIdx.x * OBLK + ol) * 4 + part] = g;
    }
}

extern "C" void kernel_launch(void* const* d_in, const int* in_sizes, int n_in,
                              void* d_out, int out_size)
{
    const float* x    = (const float*)d_in[0];
    const int*   seqL = (const int*)d_in[1];
    const float* Wm   = (const float*)d_in[2];
    const float* p    = (const float*)d_in[3];
    float* out = (float*)d_out;

    wt_kernel<<<C_DIM, O_DIM>>>(Wm);
    seg_max_kernel<<<B_SEG * C_DIM, 352>>>(x, seqL);

    dim3 grid2(O_DIM / OBLK, B_SEG);
    conv_gem_kernel<<<grid2, 192>>>(p, out);
}

// round 9
// speedup vs baseline: 1.0230x; 1.0230x over previous
#include <cuda_runtime.h>
#include <math.h>

#define C_DIM 128
#define S_DIM 4096
#define HW 176          // 16 * 11
#define HW4 44          // HW / 4
#define B_SEG 32
#define O_DIM 256
#define OSLICE 32       // o per conv-slice block
#define NSLICE 8        // conv slices per b (last NSLICE arrivers)
#define PART_LEN 44     // 4 rows * 11
#define GEM_EPS 1e-6f
#define NEG_INF -3.402823466e38f

// scratch
__device__ float g_pooled[B_SEG * C_DIM * HW];   // [b][c][hw]
__device__ int   g_cnt[B_SEG];

__device__ __forceinline__ float4 max4(float4 a, float4 b) {
    float4 r;
    r.x = fmaxf(a.x, b.x); r.y = fmaxf(a.y, b.y);
    r.z = fmaxf(a.z, b.z); r.w = fmaxf(a.w, b.w);
    return r;
}

__device__ __forceinline__ unsigned long long pack2(float v) {
    unsigned long long r;
    asm("mov.b64 %0, {%1, %1};" : "=l"(r) : "f"(v));
    return r;
}
__device__ __forceinline__ void unpack2(unsigned long long v, float& lo, float& hi) {
    asm("mov.b64 {%0, %1}, %2;" : "=f"(lo), "=f"(hi) : "l"(v));
}
__device__ __forceinline__ void ffma2(unsigned long long& d,
                                      unsigned long long a, unsigned long long b) {
    asm("fma.rn.f32x2 %0, %1, %2, %0;" : "+l"(d) : "l"(a), "l"(b));
}

// GeM power: v^pe. Fast path for pe == 6.5: (v^3)^2 * sqrt(v).
__device__ __forceinline__ float gem_pow(float x, float pe, bool fast65) {
    float v = fmaxf(x, GEM_EPS);
    if (fast65) {
        float v3 = v * v * v;
        return v3 * v3 * sqrtf(v);
    }
    return exp2f(pe * __log2f(v));
}

__global__ void zero_cnt_kernel() {
    if (threadIdx.x < B_SEG) g_cnt[threadIdx.x] = 0;
}

// ---------------------------------------------------------------------------
// Fused kernel. Grid 4096 = (b, c), 352 threads, 3 blocks/SM.
// Phase 1: ragged segment max for (b, c) — float4 streaming, MLP=8.
// Then: threadfence + atomicAdd(cnt[b]). Blocks with arrival order >= 120
// spin until cnt[b] == 128 and compute a 32-o slice of conv + GeM for b.
// Conv compute overlaps the remaining streaming of later b's.
// ---------------------------------------------------------------------------
__global__ void __launch_bounds__(352, 3) fused_kernel(
    const float* __restrict__ x, const int* __restrict__ seqL,
    const float* __restrict__ Wmat, const float* __restrict__ p,
    float* __restrict__ out)
{
    __shared__ int sh[3];                         // s0, len, order
    __shared__ float4 smax[8 * HW4];              // 5.6 KB
    __shared__ __align__(16) float ws[C_DIM * OSLICE];   // 16 KB
    __shared__ float ypow[OSLICE * HW];           // 22.5 KB
    __shared__ float pp[4];

    int blk = blockIdx.x;
    int b = blk & (B_SEG - 1);
    int c = blk >> 5;
    int tid = threadIdx.x;

    // ---- Phase 1: segment max ----
    if (tid == 0) {
        int s0 = 0;
        #pragma unroll
        for (int i = 0; i < B_SEG; i++) s0 += (i < b) ? seqL[i] : 0;
        sh[0] = s0;
        sh[1] = seqL[b];
    }
    __syncthreads();

    {
        int sg  = tid / HW4;   // 0..7
        int col = tid % HW4;   // 0..43
        int s0  = sh[0];
        int len = sh[1];

        const float4* bp = reinterpret_cast<const float4*>(x)
                         + (size_t)c * (S_DIM * HW4) + (size_t)s0 * HW4 + col;

        float4 m = make_float4(NEG_INF, NEG_INF, NEG_INF, NEG_INF);
        int s = sg;
        for (; s + 56 < len; s += 64) {
            float4 a0 = __ldcs(&bp[(size_t)(s +  0) * HW4]);
            float4 a1 = __ldcs(&bp[(size_t)(s +  8) * HW4]);
            float4 a2 = __ldcs(&bp[(size_t)(s + 16) * HW4]);
            float4 a3 = __ldcs(&bp[(size_t)(s + 24) * HW4]);
            float4 a4 = __ldcs(&bp[(size_t)(s + 32) * HW4]);
            float4 a5 = __ldcs(&bp[(size_t)(s + 40) * HW4]);
            float4 a6 = __ldcs(&bp[(size_t)(s + 48) * HW4]);
            float4 a7 = __ldcs(&bp[(size_t)(s + 56) * HW4]);
            m = max4(m, max4(max4(max4(a0, a1), max4(a2, a3)),
                             max4(max4(a4, a5), max4(a6, a7))));
        }
        for (; s < len; s += 8) {
            m = max4(m, __ldcs(&bp[(size_t)s * HW4]));
        }

        smax[sg * HW4 + col] = m;
    }
    __syncthreads();

    if (tid < HW4) {
        float4 r = smax[tid];
        #pragma unroll
        for (int g = 1; g < 8; g++) r = max4(r, smax[g * HW4 + tid]);
        reinterpret_cast<float4*>(g_pooled)[(size_t)(b * C_DIM + c) * HW4 + tid] = r;
    }
    __syncthreads();

    // ---- Publish: pooled[b][c] done ----
    if (tid == 0) {
        __threadfence();
        sh[2] = atomicAdd(&g_cnt[b], 1);
    }
    __syncthreads();
    int order = sh[2];
    if (order < C_DIM - NSLICE) return;   // not a conv block

    int o0 = (order - (C_DIM - NSLICE)) * OSLICE;

    // Stage W slice + p while (possibly) other producers finish
    if (tid < 4) pp[tid] = p[tid];
    for (int i = tid; i < C_DIM * OSLICE; i += 352) {
        int cc = i >> 5;
        int j  = i & (OSLICE - 1);
        ws[i] = Wmat[(o0 + j) * C_DIM + cc];
    }

    // Wait for all 128 producers of this b
    if (tid == 0) {
        while (*(volatile int*)&g_cnt[b] != C_DIM) __nanosleep(100);
        __threadfence();
    }
    __syncthreads();

    // ---- Phase 2: conv slice [32 o] x [176 hw] for batch b ----
    {
        int half = tid / HW;        // 0 or 1 -> o sub-slice of 16
        int hw   = tid % HW;

        unsigned long long acc[8];
        #pragma unroll
        for (int k = 0; k < 8; k++) acc[k] = 0ULL;

        const float* pb  = g_pooled + (size_t)b * C_DIM * HW + hw;
        const float* wsh = ws + half * 16;

        #pragma unroll 4
        for (int cc = 0; cc < C_DIM; cc++) {
            unsigned long long pv2 = pack2(__ldg(&pb[(size_t)cc * HW]));
            const ulonglong2* wr = reinterpret_cast<const ulonglong2*>(
                wsh + cc * OSLICE);
            ulonglong2 w0 = wr[0];
            ulonglong2 w1 = wr[1];
            ulonglong2 w2 = wr[2];
            ulonglong2 w3 = wr[3];
            ffma2(acc[0], pv2, w0.x); ffma2(acc[1], pv2, w0.y);
            ffma2(acc[2], pv2, w1.x); ffma2(acc[3], pv2, w1.y);
            ffma2(acc[4], pv2, w2.x); ffma2(acc[5], pv2, w2.y);
            ffma2(acc[6], pv2, w3.x); ffma2(acc[7], pv2, w3.y);
        }

        int part = hw / PART_LEN;
        float pe = pp[part];
        bool fast65 = (pe == 6.5f);
        int ob = half * 16;
        #pragma unroll
        for (int k = 0; k < 8; k++) {
            float lo, hi;
            unpack2(acc[k], lo, hi);
            ypow[(ob + 2 * k + 0) * HW + hw] = gem_pow(lo, pe, fast65);
            ypow[(ob + 2 * k + 1) * HW + hw] = gem_pow(hi, pe, fast65);
        }
    }
    __syncthreads();

    // 128 threads: one per (o_local, part)
    if (tid < OSLICE * 4) {
        int ol   = tid >> 2;
        int part = tid & 3;
        const float* yp = ypow + ol * HW + part * PART_LEN;
        float sum = 0.0f;
        #pragma unroll
        for (int k = 0; k < PART_LEN; k++) sum += yp[k];
        float pe = pp[part];
        float mean = sum * (1.0f / (float)PART_LEN);
        float g = (mean > 0.0f) ? exp2f(__log2f(mean) / pe) : 0.0f;
        out[((size_t)b * O_DIM + o0 + ol) * 4 + part] = g;
    }
}

extern "C" void kernel_launch(void* const* d_in, const int* in_sizes, int n_in,
                              void* d_out, int out_size)
{
    const float* x    = (const float*)d_in[0];
    const int*   seqL = (const int*)d_in[1];
    const float* Wm   = (const float*)d_in[2];
    const float* p    = (const float*)d_in[3];
    float* out = (float*)d_out;

    zero_cnt_kernel<<<1, 32>>>();
    fused_kernel<<<B_SEG * C_DIM, 352>>>(x, seqL, Wm, p, out);
}